// round 8
// baseline (speedup 1.0000x reference)
#include <cuda_runtime.h>
#include <cuda_bf16.h>
#include <math.h>
#include <stdint.h>

// ---------------------------------------------------------------------------
// xDeepFM forward. CIN via raw mma.sync bf16 3-term split (hi*hi+hi*lo+lo*hi),
// j-major K order (k' = j*39 + i), A fragments built in registers from E,C.
// W pre-split to bf16 hi/lo in n-major per-kstep layout [ks][n:224][k:16]
// so B fragments load via full-rate NON-trans ldmatrix.x4.
// K-split partial outputs; reduction FUSED into next consumer's loader.
// Launch order places cin_mma<200> at index 5 (ncu -s 5 capture slot).
// ---------------------------------------------------------------------------

#define Bsz 1024
#define NUM_NUMERIC 13
#define NUM_CAT 26
#define CARD 1000
#define Mfld 39
#define Demb 10
#define Ffeat 26013
#define Rrows (Bsz * Demb)   // 10240

#define NPAD 224
#define KPAD0 1536           // >= 39*39, 3 x 512
#define KPAD1 7840           // >= 39*200, 7 x 1120
#define SPLIT0 3
#define SPLIT1 7
#define KPER0 (KPAD0 / SPLIT0)   // 512  (32 ksteps)
#define KPER1 (KPAD1 / SPLIT1)   // 1120 (70 ksteps)
#define PSTR ((size_t)Rrows * NPAD)

// ----------------------------- scratch --------------------------------------
__device__ float g_E_dm[Rrows * Mfld];
__device__ float g_E_flat[Bsz * Mfld * Demb];
__device__ float g_linpart[27 * Bsz];
__device__ float g_pA[SPLIT0 * Rrows * NPAD];   // layer0 partials
__device__ float g_pB[SPLIT1 * Rrows * NPAD];   // layer1 partials
__device__ float g_pC[SPLIT1 * Rrows * NPAD];   // layer2 partials
__device__ float g_cinlogit[Bsz];
__device__ float g_h0[Bsz * 400];
__device__ float g_h1[Bsz * 400];

// W split, n-major per-kstep: idx = (ks*224 + n)*16 + kk
__device__ __nv_bfloat16 g_W0hi[KPAD0 * NPAD];
__device__ __nv_bfloat16 g_W0lo[KPAD0 * NPAD];
__device__ __nv_bfloat16 g_W1hi[KPAD1 * NPAD];
__device__ __nv_bfloat16 g_W1lo[KPAD1 * NPAD];
__device__ __nv_bfloat16 g_W2hi[KPAD1 * NPAD];
__device__ __nv_bfloat16 g_W2lo[KPAD1 * NPAD];

// ----------------------------- helpers --------------------------------------
__device__ __forceinline__ uint32_t smem_u32(const void* p) {
    uint32_t a;
    asm("{ .reg .u64 t; cvta.to.shared.u64 t, %1; cvt.u32.u64 %0, t; }" : "=r"(a) : "l"(p));
    return a;
}
__device__ __forceinline__ void cp_async16g(void* dst, const void* src) {
    unsigned s = (unsigned)__cvta_generic_to_shared(dst);
    asm volatile("cp.async.cg.shared.global [%0], [%1], 16;\n" :: "r"(s), "l"(src));
}
#define CP_COMMIT() asm volatile("cp.async.commit_group;\n" ::: "memory")
#define CP_WAIT0()  asm volatile("cp.async.wait_group 0;\n" ::: "memory")

__device__ __forceinline__ void ldsm_x4(uint32_t& r0, uint32_t& r1, uint32_t& r2, uint32_t& r3,
                                        uint32_t saddr) {
    asm volatile("ldmatrix.sync.aligned.m8n8.x4.shared.b16 {%0,%1,%2,%3}, [%4];"
                 : "=r"(r0), "=r"(r1), "=r"(r2), "=r"(r3) : "r"(saddr));
}
__device__ __forceinline__ void mma16816(float* c,
                                         uint32_t a0, uint32_t a1, uint32_t a2, uint32_t a3,
                                         uint32_t b0, uint32_t b1) {
    asm volatile("mma.sync.aligned.m16n8k16.row.col.f32.bf16.bf16.f32 "
                 "{%0,%1,%2,%3},{%4,%5,%6,%7},{%8,%9},{%0,%1,%2,%3};"
                 : "+f"(c[0]), "+f"(c[1]), "+f"(c[2]), "+f"(c[3])
                 : "r"(a0), "r"(a1), "r"(a2), "r"(a3), "r"(b0), "r"(b1));
}
// pack two f32 -> bf16x2 (y in upper half), rn
__device__ __forceinline__ uint32_t cvt_bf16x2(float x, float y) {
    uint32_t d;
    asm("cvt.rn.bf16x2.f32 %0, %1, %2;" : "=r"(d) : "f"(y), "f"(x));
    return d;
}

// ===========================================================================
// embeddings (numeric) + numeric linear partial
// ===========================================================================
__global__ void numeric_kernel(const float* __restrict__ x,
                               const float* __restrict__ w_lin,
                               const float* __restrict__ W_num) {
    const int b = blockIdx.x * 128 + threadIdx.x;
    const float* xr = x + (size_t)b * Ffeat;
    float lin = 0.0f;
    #pragma unroll
    for (int f = 0; f < NUM_NUMERIC; ++f) {
        float xv = xr[f];
        lin += xv * w_lin[f];
        #pragma unroll
        for (int d = 0; d < Demb; ++d) {
            float v = xv * W_num[f * Demb + d];
            g_E_flat[b * (Mfld * Demb) + f * Demb + d] = v;
            g_E_dm[(b * Demb + d) * Mfld + f] = v;
        }
    }
    g_linpart[26 * Bsz + b] = lin;
}

// ===========================================================================
// categorical embeddings (skinny GEMMs) + per-field linear partials
// ===========================================================================
__global__ __launch_bounds__(256)
void cat_kernel(const float* __restrict__ x,
                const float* __restrict__ w_lin,
                const float* __restrict__ W_cat) {
    __shared__ float Xs[64 * 130];
    __shared__ float Ws[64 * 10];
    __shared__ float Ls[64];

    const int t    = threadIdx.x;
    const int f    = blockIdx.y;
    const int b0   = blockIdx.x * 128;
    const int r    = t & 127;
    const int half = t >> 7;
    const int d0   = half * 5;

    float acc[5] = {0.f, 0.f, 0.f, 0.f, 0.f};
    float lin = 0.0f;

    for (int k0 = 0; k0 < CARD; k0 += 64) {
        const int kc = min(64, CARD - k0);
        __syncthreads();
        for (int idx = t; idx < 128 * 64; idx += 256) {
            int rr = idx >> 6, c = idx & 63;
            float v = (c < kc) ? x[(size_t)(b0 + rr) * Ffeat + NUM_NUMERIC + f * CARD + k0 + c] : 0.0f;
            Xs[c * 130 + rr] = v;
        }
        for (int idx = t; idx < 640; idx += 256) {
            int kk = idx / 10, d = idx - kk * 10;
            Ws[idx] = (kk < kc) ? W_cat[(size_t)(f * CARD + k0 + kk) * Demb + d] : 0.0f;
        }
        if (t < 64) Ls[t] = (t < kc) ? w_lin[NUM_NUMERIC + f * CARD + k0 + t] : 0.0f;
        __syncthreads();

        #pragma unroll 8
        for (int kk = 0; kk < 64; ++kk) {
            float xv = Xs[kk * 130 + r];
            if (half == 0) lin += xv * Ls[kk];
            #pragma unroll
            for (int q = 0; q < 5; ++q) acc[q] += xv * Ws[kk * 10 + d0 + q];
        }
    }

    const int b = b0 + r;
    const int fld = NUM_NUMERIC + f;
    #pragma unroll
    for (int q = 0; q < 5; ++q) {
        int d = d0 + q;
        g_E_flat[b * (Mfld * Demb) + fld * Demb + d] = acc[q];
        g_E_dm[(b * Demb + d) * Mfld + fld] = acc[q];
    }
    if (half == 0) g_linpart[f * Bsz + b] = lin;
}

// ===========================================================================
// W split to bf16 hi/lo, n-major per-kstep layout: out[(ks*224+n)*16+kk]
// from W[(i*HIN+j)*200+n], k' = ks*16+kk = j*39+i.
// ===========================================================================
__global__ void convert_w(const float* __restrict__ W,
                          __nv_bfloat16* __restrict__ Whi,
                          __nv_bfloat16* __restrict__ Wlo,
                          int HIN, int KPAD) {
    int idx = blockIdx.x * 256 + threadIdx.x;
    if (idx >= KPAD * NPAD) return;
    int ks  = idx / (NPAD * 16);
    int rem = idx - ks * (NPAD * 16);
    int n   = rem >> 4;
    int kk  = rem & 15;
    int kp  = ks * 16 + kk;
    int j   = kp / 39;
    int i   = kp - j * 39;
    float v = (j < HIN && n < 200) ? W[(size_t)(i * HIN + j) * 200 + n] : 0.0f;
    __nv_bfloat16 h = __float2bfloat16_rn(v);
    Whi[idx] = h;
    Wlo[idx] = __float2bfloat16_rn(v - __bfloat162float(h));
}

// ===========================================================================
// CIN GEMM: mma.sync bf16 3-term split, A built in registers.
// Block 64 rows x 224 cols, 8 warps (wm4 x wn2), warp 16m x 112n.
// NSRC=0: C read from Cmat directly. NSRC>0: C = bias + sum of NSRC partial
// slices (fused reduction of previous layer's K-split outputs).
// ===========================================================================
template <int HIN, int KPER, int JS, int NSRC>
__global__ void __launch_bounds__(256, 2)
cin_mma(const float* __restrict__ Cmat,       // NSRC=0: (Rrows,HIN). else: partials base
        const float* __restrict__ cbias,      // bias for fused reduce (NSRC>0)
        const __nv_bfloat16* __restrict__ Whi,
        const __nv_bfloat16* __restrict__ Wlo,
        float* __restrict__ part) {
    constexpr int NK     = KPER / 16;
    constexpr int CSTR   = JS + 1;
    constexpr int ES_OFF = 64 * CSTR * 4;
    constexpr int B_OFF  = ((ES_OFF + 64 * 39 * 4 + 127) / 128) * 128;
    constexpr int B_HALF = 224 * 32;                 // 7168 B (n-major, 32B per n)
    constexpr int B_STRIDE = 2 * B_HALF;             // hi+lo
    constexpr int TAB_OFF = B_OFF + 2 * B_STRIDE;

    extern __shared__ char sm[];
    float* Cs = (float*)sm;
    float* Es = (float*)(sm + ES_OFF);
    uint32_t* sTab = (uint32_t*)(sm + TAB_OFF);
    const uint32_t smb = smem_u32(sm);

    const int tid  = threadIdx.x;
    const int lane = tid & 31;
    const int wid  = tid >> 5;
    const int wm   = wid & 3;
    const int wn   = wid >> 2;
    const int g    = lane >> 2;
    const int tig  = lane & 3;
    const int row0 = blockIdx.x * 64;
    const int kbase = blockIdx.y * KPER;
    const int jbase = kbase / 39;

    // ---- C tile (with optional fused reduction of previous partials) ----
    if (NSRC == 0) {
        for (int idx = tid; idx < 64 * JS; idx += 256) {
            int m = idx / JS, jj = idx - m * JS;
            int j = jbase + jj;
            Cs[m * CSTR + jj] = (j < HIN) ? Cmat[(size_t)(row0 + m) * HIN + j] : 0.0f;
        }
    } else {
        for (int idx = tid; idx < 64 * JS; idx += 256) {
            int m = idx / JS, jj = idx - m * JS;
            int j = jbase + jj;
            float v = 0.0f;
            if (j < HIN) {
                v = cbias[j];
                size_t off = (size_t)(row0 + m) * NPAD + j;
                #pragma unroll
                for (int s = 0; s < NSRC; ++s) v += Cmat[(size_t)s * PSTR + off];
            }
            Cs[m * CSTR + jj] = v;
        }
    }
    // ---- E tile ----
    for (int idx = tid; idx < 64 * 39; idx += 256) {
        int m = idx / 39, i = idx - m * 39;
        Es[m * 39 + i] = g_E_dm[(size_t)(row0 + m) * 39 + i];
    }
    // ---- (i,jj) table ----
    for (int t = tid; t < KPER; t += 256) {
        int kg = kbase + t;
        int j = kg / 39;
        int i = kg - j * 39;
        sTab[t] = (uint32_t)i | ((uint32_t)(j - jbase) << 8);
    }

    auto load_B = [&](int ks, int buf) {
        char* base = sm + B_OFF + buf * B_STRIDE;
        const size_t src0 = (size_t)(kbase / 16 + ks) * (NPAD * 16);
        for (int idx = tid; idx < 896; idx += 256) {
            int half = (idx >= 448) ? 1 : 0;
            int rem  = idx - half * 448;          // rem = n*2 + q  (q: 8-element half of 16k)
            const __nv_bfloat16* src = (half ? Wlo : Whi) + src0 + rem * 8;
            cp_async16g(base + half * B_HALF + rem * 16, src);
        }
        CP_COMMIT();
    };

    load_B(0, 0);
    CP_WAIT0();
    __syncthreads();

    float acc[14][4];
    #pragma unroll
    for (int p = 0; p < 14; ++p)
        #pragma unroll
        for (int q = 0; q < 4; ++q) acc[p][q] = 0.0f;

    const int m0 = wm * 16 + g;
    const int m1 = m0 + 8;
    // non-trans ldmatrix lane address (within a half-buffer):
    //   n_row = wn*112 + (lane&7) + ((lane>>4)&1)*8 ; +16B if lane bit3 (k 8..15)
    const uint32_t lB = (uint32_t)((wn * 112 + (lane & 7) + ((lane >> 4) & 1) * 8) * 32
                                   + ((lane >> 3) & 1) * 16);

    for (int ks = 0; ks < NK; ++ks) {
        const int buf = ks & 1;
        if (ks + 1 < NK) load_B(ks + 1, buf ^ 1);

        // ---- build A fragments (hi/lo) in registers ----
        uint32_t ah[4], al[4];
        {
            const uint32_t* tp = sTab + ks * 16;
            uint32_t t0 = tp[tig * 2], t1 = tp[tig * 2 + 1];
            uint32_t t2 = tp[tig * 2 + 8], t3 = tp[tig * 2 + 9];
            float v00 = Es[m0 * 39 + (t0 & 0xFF)] * Cs[m0 * CSTR + (t0 >> 8)];
            float v01 = Es[m0 * 39 + (t1 & 0xFF)] * Cs[m0 * CSTR + (t1 >> 8)];
            float v02 = Es[m0 * 39 + (t2 & 0xFF)] * Cs[m0 * CSTR + (t2 >> 8)];
            float v03 = Es[m0 * 39 + (t3 & 0xFF)] * Cs[m0 * CSTR + (t3 >> 8)];
            float v10 = Es[m1 * 39 + (t0 & 0xFF)] * Cs[m1 * CSTR + (t0 >> 8)];
            float v11 = Es[m1 * 39 + (t1 & 0xFF)] * Cs[m1 * CSTR + (t1 >> 8)];
            float v12 = Es[m1 * 39 + (t2 & 0xFF)] * Cs[m1 * CSTR + (t2 >> 8)];
            float v13 = Es[m1 * 39 + (t3 & 0xFF)] * Cs[m1 * CSTR + (t3 >> 8)];
            ah[0] = cvt_bf16x2(v00, v01);
            ah[1] = cvt_bf16x2(v10, v11);
            ah[2] = cvt_bf16x2(v02, v03);
            ah[3] = cvt_bf16x2(v12, v13);
            // residuals: bf16 bits are the top 16 of fp32
            al[0] = cvt_bf16x2(v00 - __uint_as_float(ah[0] << 16),
                               v01 - __uint_as_float(ah[0] & 0xFFFF0000u));
            al[1] = cvt_bf16x2(v10 - __uint_as_float(ah[1] << 16),
                               v11 - __uint_as_float(ah[1] & 0xFFFF0000u));
            al[2] = cvt_bf16x2(v02 - __uint_as_float(ah[2] << 16),
                               v03 - __uint_as_float(ah[2] & 0xFFFF0000u));
            al[3] = cvt_bf16x2(v12 - __uint_as_float(ah[3] << 16),
                               v13 - __uint_as_float(ah[3] & 0xFFFF0000u));
        }

        // ---- MMAs over 7 n-tiles ----
        const uint32_t bs = smb + B_OFF + buf * B_STRIDE + lB;
        #pragma unroll
        for (int nt = 0; nt < 7; ++nt) {
            uint32_t r0, r1, r2, r3, s0, s1, s2, s3;
            ldsm_x4(r0, r1, r2, r3, bs + nt * 512);              // Bhi
            ldsm_x4(s0, s1, s2, s3, bs + B_HALF + nt * 512);     // Blo
            mma16816(acc[nt * 2],     ah[0], ah[1], ah[2], ah[3], r0, r1);
            mma16816(acc[nt * 2 + 1], ah[0], ah[1], ah[2], ah[3], r2, r3);
            mma16816(acc[nt * 2],     ah[0], ah[1], ah[2], ah[3], s0, s1);
            mma16816(acc[nt * 2 + 1], ah[0], ah[1], ah[2], ah[3], s2, s3);
            mma16816(acc[nt * 2],     al[0], al[1], al[2], al[3], r0, r1);
            mma16816(acc[nt * 2 + 1], al[0], al[1], al[2], al[3], r2, r3);
        }

        CP_WAIT0();
        __syncthreads();
    }

    // ---- epilogue: store partials ----
    float* op = part + (size_t)blockIdx.y * PSTR;
    #pragma unroll
    for (int nt = 0; nt < 7; ++nt)
        #pragma unroll
        for (int nh = 0; nh < 2; ++nh) {
            const float* c = acc[nt * 2 + nh];
            int col = wn * 112 + nt * 16 + nh * 8 + tig * 2;
            size_t r = (size_t)(row0 + wm * 16 + g);
            *(float2*)&op[r * NPAD + col]       = make_float2(c[0], c[1]);
            *(float2*)&op[(r + 8) * NPAD + col] = make_float2(c[2], c[3]);
        }
}

// ===========================================================================
// CIN pooling + cin linear, reading K-split partials directly.
//   pooled_l[b,h] = 10*bias_l[h] + sum_{d,s} part_l[s][(b*10+d)*224+h]
// ===========================================================================
__global__ void pool_kernel(const float* __restrict__ cin_lin_w,
                            const float* __restrict__ b0,
                            const float* __restrict__ b1,
                            const float* __restrict__ b2) {
    const int b = blockIdx.x;
    const int tid = threadIdx.x;

    float acc = 0.0f;
    // layer sums: for each (l,d,h) add partial slices
    for (int j = tid; j < 3 * Demb * 200; j += 256) {
        int l = j / 2000;
        int rem = j - l * 2000;
        int d = rem / 200;
        int h = rem - d * 200;
        size_t off = (size_t)(b * Demb + d) * NPAD + h;
        float w = cin_lin_w[l * 200 + h];
        float v = 0.0f;
        if (l == 0) {
            #pragma unroll
            for (int s = 0; s < SPLIT0; ++s) v += g_pA[(size_t)s * PSTR + off];
            if (d == 0) v += Demb * b0[h];
        } else if (l == 1) {
            #pragma unroll
            for (int s = 0; s < SPLIT1; ++s) v += g_pB[(size_t)s * PSTR + off];
            if (d == 0) v += Demb * b1[h];
        } else {
            #pragma unroll
            for (int s = 0; s < SPLIT1; ++s) v += g_pC[(size_t)s * PSTR + off];
            if (d == 0) v += Demb * b2[h];
        }
        acc += v * w;
    }
    __shared__ float red[256];
    red[tid] = acc;
    __syncthreads();
    for (int s = 128; s > 0; s >>= 1) {
        if (tid < s) red[tid] += red[tid + s];
        __syncthreads();
    }
    if (tid == 0) g_cinlogit[b] = red[0];
}

// ===========================================================================
// DNN GEMM + optional relu
// ===========================================================================
__global__ void dnn_gemm(const float* __restrict__ A,
                         const float* __restrict__ W,
                         const float* __restrict__ bias,
                         float* __restrict__ Out,
                         int K, int relu) {
    __shared__ float As[16 * 64];
    __shared__ float Bs[16 * 40];

    const int tid = threadIdx.x;
    const int row0 = blockIdx.x * 64;
    const int n0 = blockIdx.y * 40;
    const int tx = tid & 7;
    const int ty = tid >> 3;
    const int N = 400;

    float acc[2][5];
    #pragma unroll
    for (int m = 0; m < 2; ++m)
        #pragma unroll
        for (int q = 0; q < 5; ++q) acc[m][q] = 0.0f;

    for (int k0 = 0; k0 < K; k0 += 16) {
        __syncthreads();
        for (int idx = tid; idx < 64 * 16; idx += 256) {
            int r = idx >> 4, kk = idx & 15;
            int k = k0 + kk;
            As[kk * 64 + r] = (k < K) ? A[(size_t)(row0 + r) * K + k] : 0.0f;
        }
        for (int idx = tid; idx < 16 * 40; idx += 256) {
            int kk = idx / 40, q = idx - kk * 40;
            int k = k0 + kk;
            Bs[kk * 40 + q] = (k < K) ? W[(size_t)k * N + n0 + q] : 0.0f;
        }
        __syncthreads();

        #pragma unroll
        for (int kk = 0; kk < 16; ++kk) {
            float a0 = As[kk * 64 + ty * 2 + 0];
            float a1 = As[kk * 64 + ty * 2 + 1];
            float wv[5];
            #pragma unroll
            for (int q = 0; q < 5; ++q) wv[q] = Bs[kk * 40 + tx * 5 + q];
            #pragma unroll
            for (int q = 0; q < 5; ++q) {
                acc[0][q] += a0 * wv[q];
                acc[1][q] += a1 * wv[q];
            }
        }
    }

    #pragma unroll
    for (int m = 0; m < 2; ++m) {
        int r = row0 + ty * 2 + m;
        #pragma unroll
        for (int q = 0; q < 5; ++q) {
            int n = n0 + tx * 5 + q;
            float v = acc[m][q] + bias[n];
            if (relu) v = fmaxf(v, 0.0f);
            Out[(size_t)r * N + n] = v;
        }
    }
}

// ===========================================================================
// Final: dnn linear dot + linear partials + combine + sigmoid
// ===========================================================================
__global__ void final_kernel(const float* __restrict__ b_lin,
                             const float* __restrict__ cin_lin_b,
                             const float* __restrict__ dnn_lin_w,
                             const float* __restrict__ dnn_lin_b,
                             const float* __restrict__ pred_b,
                             float* __restrict__ out) {
    const int b = blockIdx.x;
    const int tid = threadIdx.x;
    float acc = 0.0f;
    for (int k = tid; k < 400; k += 128)
        acc += g_h1[(size_t)b * 400 + k] * dnn_lin_w[k];
    for (int f = tid; f < 27; f += 128)
        acc += g_linpart[f * Bsz + b];
    __shared__ float red[128];
    red[tid] = acc;
    __syncthreads();
    for (int s = 64; s > 0; s >>= 1) {
        if (tid < s) red[tid] += red[tid + s];
        __syncthreads();
    }
    if (tid == 0) {
        float z = red[0] + b_lin[0]
                + g_cinlogit[b] + cin_lin_b[0]
                + dnn_lin_b[0] + pred_b[0];
        out[b] = 1.0f / (1.0f + expf(-z));
    }
}

// ===========================================================================
// host launcher
// ===========================================================================
static int smem_cin(int JS, int KPER) {
    int cstr = JS + 1;
    int es_off = 64 * cstr * 4;
    int b_off = ((es_off + 64 * 39 * 4 + 127) / 128) * 128;
    int tab_off = b_off + 2 * (2 * 224 * 32);
    return tab_off + KPER * 4;
}

extern "C" void kernel_launch(void* const* d_in, const int* in_sizes, int n_in,
                              void* d_out, int out_size) {
    const float* x         = (const float*)d_in[0];
    const float* w_lin     = (const float*)d_in[1];
    const float* b_lin     = (const float*)d_in[2];
    const float* W_num     = (const float*)d_in[3];
    const float* W_cat     = (const float*)d_in[4];
    const float* cin_w0    = (const float*)d_in[5];
    const float* cin_b0    = (const float*)d_in[6];
    const float* cin_w1    = (const float*)d_in[7];
    const float* cin_b1    = (const float*)d_in[8];
    const float* cin_w2    = (const float*)d_in[9];
    const float* cin_b2    = (const float*)d_in[10];
    const float* cin_lin_w = (const float*)d_in[11];
    const float* cin_lin_b = (const float*)d_in[12];
    const float* dnn_w0    = (const float*)d_in[13];
    const float* dnn_b0    = (const float*)d_in[14];
    const float* dnn_w1    = (const float*)d_in[15];
    const float* dnn_b1    = (const float*)d_in[16];
    const float* dnn_lin_w = (const float*)d_in[17];
    const float* dnn_lin_b = (const float*)d_in[18];
    const float* pred_b    = (const float*)d_in[19];
    float* out = (float*)d_out;

    float *p_E_dm, *p_E_flat, *p_h0, *p_h1, *p_pA, *p_pB, *p_pC;
    cudaGetSymbolAddress((void**)&p_E_dm,   g_E_dm);
    cudaGetSymbolAddress((void**)&p_E_flat, g_E_flat);
    cudaGetSymbolAddress((void**)&p_h0,     g_h0);
    cudaGetSymbolAddress((void**)&p_h1,     g_h1);
    cudaGetSymbolAddress((void**)&p_pA,     g_pA);
    cudaGetSymbolAddress((void**)&p_pB,     g_pB);
    cudaGetSymbolAddress((void**)&p_pC,     g_pC);

    __nv_bfloat16 *p_W0hi, *p_W0lo, *p_W1hi, *p_W1lo, *p_W2hi, *p_W2lo;
    cudaGetSymbolAddress((void**)&p_W0hi, g_W0hi);
    cudaGetSymbolAddress((void**)&p_W0lo, g_W0lo);
    cudaGetSymbolAddress((void**)&p_W1hi, g_W1hi);
    cudaGetSymbolAddress((void**)&p_W1lo, g_W1lo);
    cudaGetSymbolAddress((void**)&p_W2hi, g_W2hi);
    cudaGetSymbolAddress((void**)&p_W2lo, g_W2lo);

    const int SM0 = smem_cin(14, KPER0);
    const int SM1 = smem_cin(30, KPER1);
    cudaFuncSetAttribute(cin_mma<39,  KPER0, 14, 0>,      cudaFuncAttributeMaxDynamicSharedMemorySize, SM0);
    cudaFuncSetAttribute(cin_mma<200, KPER1, 30, SPLIT0>, cudaFuncAttributeMaxDynamicSharedMemorySize, SM1);
    cudaFuncSetAttribute(cin_mma<200, KPER1, 30, SPLIT1>, cudaFuncAttributeMaxDynamicSharedMemorySize, SM1);

    const int ROWB = Rrows / 64;   // 160

    // Launch order chosen so cin_mma<200> layer1 is launch index 5 (ncu -s 5).
    numeric_kernel<<<Bsz / 128, 128>>>(x, w_lin, W_num);                                    // 0
    cat_kernel<<<dim3(Bsz / 128, NUM_CAT), 256>>>(x, w_lin, W_cat);                         // 1
    convert_w<<<(KPAD0 * NPAD + 255) / 256, 256>>>(cin_w0, p_W0hi, p_W0lo, 39,  KPAD0);     // 2
    convert_w<<<(KPAD1 * NPAD + 255) / 256, 256>>>(cin_w1, p_W1hi, p_W1lo, 200, KPAD1);     // 3
    cin_mma<39,  KPER0, 14, 0><<<dim3(ROWB, SPLIT0), 256, SM0>>>(                           // 4
        p_E_dm, nullptr, p_W0hi, p_W0lo, p_pA);
    cin_mma<200, KPER1, 30, SPLIT0><<<dim3(ROWB, SPLIT1), 256, SM1>>>(                      // 5  <- ncu capture
        p_pA, cin_b0, p_W1hi, p_W1lo, p_pB);
    convert_w<<<(KPAD1 * NPAD + 255) / 256, 256>>>(cin_w2, p_W2hi, p_W2lo, 200, KPAD1);     // 6
    cin_mma<200, KPER1, 30, SPLIT1><<<dim3(ROWB, SPLIT1), 256, SM1>>>(                      // 7
        p_pB, cin_b1, p_W2hi, p_W2lo, p_pC);
    pool_kernel<<<Bsz, 256>>>(cin_lin_w, cin_b0, cin_b1, cin_b2);                           // 8
    dim3 dgrid(Bsz / 64, 400 / 40);
    dnn_gemm<<<dgrid, 256>>>(p_E_flat, dnn_w0, dnn_b0, p_h0, Mfld * Demb, 1);               // 9
    dnn_gemm<<<dgrid, 256>>>(p_h0, dnn_w1, dnn_b1, p_h1, 400, 1);                           // 10
    final_kernel<<<Bsz, 128>>>(b_lin, cin_lin_b, dnn_lin_w, dnn_lin_b, pred_b, out);        // 11
}

// round 10
// speedup vs baseline: 1.3506x; 1.3506x over previous
#include <cuda_runtime.h>
#include <cuda_fp16.h>
#include <math.h>
#include <stdint.h>

// ---------------------------------------------------------------------------
// xDeepFM forward. CIN via raw mma.sync fp16 SINGLE (no split), fp32 accum.
//   k' = j*39 + i ; A[r,k'] = E'[r,i]*C[r,j] built in registers.
//   W converted to fp16, n-major per-kstep layout [ks][n:224][k:16]
//   (full-rate non-trans ldmatrix.x4). K-split partials, reduce fused into
//   next consumer's loader / pool kernel.
// fp16 element rounding 2^-12 -> expected rel_err ~1e-4 (gate 1e-3).
// ---------------------------------------------------------------------------

#define Bsz 1024
#define NUM_NUMERIC 13
#define NUM_CAT 26
#define CARD 1000
#define Mfld 39
#define Demb 10
#define Ffeat 26013
#define Rrows (Bsz * Demb)   // 10240

#define NPAD 224
#define KPAD0 1536           // 3 x 512
#define KPAD1 7840           // 7 x 1120
#define SPLIT0 3
#define SPLIT1 7
#define KPER0 (KPAD0 / SPLIT0)
#define KPER1 (KPAD1 / SPLIT1)
#define PSTR ((size_t)Rrows * NPAD)

// ----------------------------- scratch --------------------------------------
__device__ float g_E_dm[Rrows * Mfld];
__device__ float g_E_flat[Bsz * Mfld * Demb];
__device__ float g_linpart[27 * Bsz];
__device__ float g_pA[SPLIT0 * Rrows * NPAD];
__device__ float g_pB[SPLIT1 * Rrows * NPAD];
__device__ float g_pC[SPLIT1 * Rrows * NPAD];
__device__ float g_cinlogit[Bsz];
__device__ float g_h0[Bsz * 400];
__device__ float g_h1[Bsz * 400];

// W fp16, n-major per-kstep: idx = (ks*224 + n)*16 + kk
__device__ __half g_W0[KPAD0 * NPAD];
__device__ __half g_W1[KPAD1 * NPAD];
__device__ __half g_W2[KPAD1 * NPAD];

// ----------------------------- helpers --------------------------------------
__device__ __forceinline__ uint32_t smem_u32(const void* p) {
    uint32_t a;
    asm("{ .reg .u64 t; cvta.to.shared.u64 t, %1; cvt.u32.u64 %0, t; }" : "=r"(a) : "l"(p));
    return a;
}
__device__ __forceinline__ void cp_async16g(void* dst, const void* src) {
    unsigned s = (unsigned)__cvta_generic_to_shared(dst);
    asm volatile("cp.async.cg.shared.global [%0], [%1], 16;\n" :: "r"(s), "l"(src));
}
#define CP_COMMIT() asm volatile("cp.async.commit_group;\n" ::: "memory")
#define CP_WAIT0()  asm volatile("cp.async.wait_group 0;\n" ::: "memory")

__device__ __forceinline__ void ldsm_x4(uint32_t& r0, uint32_t& r1, uint32_t& r2, uint32_t& r3,
                                        uint32_t saddr) {
    asm volatile("ldmatrix.sync.aligned.m8n8.x4.shared.b16 {%0,%1,%2,%3}, [%4];"
                 : "=r"(r0), "=r"(r1), "=r"(r2), "=r"(r3) : "r"(saddr));
}
__device__ __forceinline__ void mma16816h(float* c,
                                          uint32_t a0, uint32_t a1, uint32_t a2, uint32_t a3,
                                          uint32_t b0, uint32_t b1) {
    asm volatile("mma.sync.aligned.m16n8k16.row.col.f32.f16.f16.f32 "
                 "{%0,%1,%2,%3},{%4,%5,%6,%7},{%8,%9},{%0,%1,%2,%3};"
                 : "+f"(c[0]), "+f"(c[1]), "+f"(c[2]), "+f"(c[3])
                 : "r"(a0), "r"(a1), "r"(a2), "r"(a3), "r"(b0), "r"(b1));
}
__device__ __forceinline__ uint32_t cvt_f16x2(float x, float y) {
    uint32_t d;
    asm("cvt.rn.f16x2.f32 %0, %1, %2;" : "=r"(d) : "f"(y), "f"(x));
    return d;
}

// ===========================================================================
// embeddings (numeric) + numeric linear partial
// ===========================================================================
__global__ void numeric_kernel(const float* __restrict__ x,
                               const float* __restrict__ w_lin,
                               const float* __restrict__ W_num) {
    const int b = blockIdx.x * 128 + threadIdx.x;
    const float* xr = x + (size_t)b * Ffeat;
    float lin = 0.0f;
    #pragma unroll
    for (int f = 0; f < NUM_NUMERIC; ++f) {
        float xv = xr[f];
        lin += xv * w_lin[f];
        #pragma unroll
        for (int d = 0; d < Demb; ++d) {
            float v = xv * W_num[f * Demb + d];
            g_E_flat[b * (Mfld * Demb) + f * Demb + d] = v;
            g_E_dm[(b * Demb + d) * Mfld + f] = v;
        }
    }
    g_linpart[26 * Bsz + b] = lin;
}

// ===========================================================================
// categorical embeddings (skinny GEMMs) + per-field linear partials
// ===========================================================================
__global__ __launch_bounds__(256)
void cat_kernel(const float* __restrict__ x,
                const float* __restrict__ w_lin,
                const float* __restrict__ W_cat) {
    __shared__ float Xs[64 * 130];
    __shared__ float Ws[64 * 10];
    __shared__ float Ls[64];

    const int t    = threadIdx.x;
    const int f    = blockIdx.y;
    const int b0   = blockIdx.x * 128;
    const int r    = t & 127;
    const int half = t >> 7;
    const int d0   = half * 5;

    float acc[5] = {0.f, 0.f, 0.f, 0.f, 0.f};
    float lin = 0.0f;

    for (int k0 = 0; k0 < CARD; k0 += 64) {
        const int kc = min(64, CARD - k0);
        __syncthreads();
        for (int idx = t; idx < 128 * 64; idx += 256) {
            int rr = idx >> 6, c = idx & 63;
            float v = (c < kc) ? x[(size_t)(b0 + rr) * Ffeat + NUM_NUMERIC + f * CARD + k0 + c] : 0.0f;
            Xs[c * 130 + rr] = v;
        }
        for (int idx = t; idx < 640; idx += 256) {
            int kk = idx / 10, d = idx - kk * 10;
            Ws[idx] = (kk < kc) ? W_cat[(size_t)(f * CARD + k0 + kk) * Demb + d] : 0.0f;
        }
        if (t < 64) Ls[t] = (t < kc) ? w_lin[NUM_NUMERIC + f * CARD + k0 + t] : 0.0f;
        __syncthreads();

        #pragma unroll 8
        for (int kk = 0; kk < 64; ++kk) {
            float xv = Xs[kk * 130 + r];
            if (half == 0) lin += xv * Ls[kk];
            #pragma unroll
            for (int q = 0; q < 5; ++q) acc[q] += xv * Ws[kk * 10 + d0 + q];
        }
    }

    const int b = b0 + r;
    const int fld = NUM_NUMERIC + f;
    #pragma unroll
    for (int q = 0; q < 5; ++q) {
        int d = d0 + q;
        g_E_flat[b * (Mfld * Demb) + fld * Demb + d] = acc[q];
        g_E_dm[(b * Demb + d) * Mfld + fld] = acc[q];
    }
    if (half == 0) g_linpart[f * Bsz + b] = lin;
}

// ===========================================================================
// W convert to fp16, n-major per-kstep: out[(ks*224+n)*16+kk],
// k' = ks*16+kk = j*39+i, from W[(i*HIN+j)*200+n].
// ===========================================================================
__global__ void convert_w(const float* __restrict__ W,
                          __half* __restrict__ Wh,
                          int HIN, int KPAD) {
    int idx = blockIdx.x * 256 + threadIdx.x;
    if (idx >= KPAD * NPAD) return;
    int ks  = idx / (NPAD * 16);
    int rem = idx - ks * (NPAD * 16);
    int n   = rem >> 4;
    int kk  = rem & 15;
    int kp  = ks * 16 + kk;
    int j   = kp / 39;
    int i   = kp - j * 39;
    float v = (j < HIN && n < 200) ? W[(size_t)(i * HIN + j) * 200 + n] : 0.0f;
    Wh[idx] = __float2half_rn(v);
}

// ===========================================================================
// CIN GEMM: mma.sync fp16 single, A built in registers.
// Block 64 rows x 224 cols, 8 warps (wm4 x wn2), warp 16m x 112n.
// NSRC=0: C from Cmat. NSRC>0: C = bias + sum of NSRC partial slices.
// ===========================================================================
template <int HIN, int KPER, int JS, int NSRC>
__global__ void __launch_bounds__(256, 2)
cin_mma(const float* __restrict__ Cmat,
        const float* __restrict__ cbias,
        const __half* __restrict__ Wh,
        float* __restrict__ part) {
    constexpr int NK     = KPER / 16;
    constexpr int CSTR   = JS + 1;
    constexpr int ES_OFF = 64 * CSTR * 4;
    constexpr int B_OFF  = ((ES_OFF + 64 * 39 * 4 + 127) / 128) * 128;
    constexpr int B_BUF  = 224 * 32;                 // 7168 B per buffer
    constexpr int TAB_OFF = B_OFF + 2 * B_BUF;

    extern __shared__ char sm[];
    float* Cs = (float*)sm;
    float* Es = (float*)(sm + ES_OFF);
    uint32_t* sTab = (uint32_t*)(sm + TAB_OFF);
    const uint32_t smb = smem_u32(sm);

    const int tid  = threadIdx.x;
    const int lane = tid & 31;
    const int wid  = tid >> 5;
    const int wm   = wid & 3;
    const int wn   = wid >> 2;
    const int g    = lane >> 2;
    const int tig  = lane & 3;
    const int row0 = blockIdx.x * 64;
    const int kbase = blockIdx.y * KPER;
    const int jbase = kbase / 39;

    // ---- C tile (optionally fused reduction of previous partials) ----
    if (NSRC == 0) {
        for (int idx = tid; idx < 64 * JS; idx += 256) {
            int m = idx / JS, jj = idx - m * JS;
            int j = jbase + jj;
            Cs[m * CSTR + jj] = (j < HIN) ? Cmat[(size_t)(row0 + m) * HIN + j] : 0.0f;
        }
    } else {
        for (int idx = tid; idx < 64 * JS; idx += 256) {
            int m = idx / JS, jj = idx - m * JS;
            int j = jbase + jj;
            float v = 0.0f;
            if (j < HIN) {
                v = cbias[j];
                size_t off = (size_t)(row0 + m) * NPAD + j;
                #pragma unroll
                for (int s = 0; s < NSRC; ++s) v += Cmat[(size_t)s * PSTR + off];
            }
            Cs[m * CSTR + jj] = v;
        }
    }
    for (int idx = tid; idx < 64 * 39; idx += 256) {
        int m = idx / 39, i = idx - m * 39;
        Es[m * 39 + i] = g_E_dm[(size_t)(row0 + m) * 39 + i];
    }
    for (int t = tid; t < KPER; t += 256) {
        int kg = kbase + t;
        int j = kg / 39;
        int i = kg - j * 39;
        sTab[t] = (uint32_t)i | ((uint32_t)(j - jbase) << 8);
    }

    auto load_B = [&](int ks, int buf) {
        char* base = sm + B_OFF + buf * B_BUF;
        const size_t src0 = (size_t)(kbase / 16 + ks) * (NPAD * 16);
        for (int idx = tid; idx < 448; idx += 256) {
            const __half* src = Wh + src0 + idx * 8;
            cp_async16g(base + idx * 16, src);
        }
        CP_COMMIT();
    };

    load_B(0, 0);
    CP_WAIT0();
    __syncthreads();

    float acc[14][4];
    #pragma unroll
    for (int p = 0; p < 14; ++p)
        #pragma unroll
        for (int q = 0; q < 4; ++q) acc[p][q] = 0.0f;

    const int m0 = wm * 16 + g;
    const int m1 = m0 + 8;
    const uint32_t lB = (uint32_t)((wn * 112 + (lane & 7) + ((lane >> 4) & 1) * 8) * 32
                                   + ((lane >> 3) & 1) * 16);

    for (int ks = 0; ks < NK; ++ks) {
        const int buf = ks & 1;
        if (ks + 1 < NK) load_B(ks + 1, buf ^ 1);

        // ---- A fragments (fp16) ----
        uint32_t a0, a1, a2, a3;
        {
            const uint32_t* tp = sTab + ks * 16;
            uint32_t t0 = tp[tig * 2], t1 = tp[tig * 2 + 1];
            uint32_t t2 = tp[tig * 2 + 8], t3 = tp[tig * 2 + 9];
            float v00 = Es[m0 * 39 + (t0 & 0xFF)] * Cs[m0 * CSTR + (t0 >> 8)];
            float v01 = Es[m0 * 39 + (t1 & 0xFF)] * Cs[m0 * CSTR + (t1 >> 8)];
            float v02 = Es[m0 * 39 + (t2 & 0xFF)] * Cs[m0 * CSTR + (t2 >> 8)];
            float v03 = Es[m0 * 39 + (t3 & 0xFF)] * Cs[m0 * CSTR + (t3 >> 8)];
            float v10 = Es[m1 * 39 + (t0 & 0xFF)] * Cs[m1 * CSTR + (t0 >> 8)];
            float v11 = Es[m1 * 39 + (t1 & 0xFF)] * Cs[m1 * CSTR + (t1 >> 8)];
            float v12 = Es[m1 * 39 + (t2 & 0xFF)] * Cs[m1 * CSTR + (t2 >> 8)];
            float v13 = Es[m1 * 39 + (t3 & 0xFF)] * Cs[m1 * CSTR + (t3 >> 8)];
            a0 = cvt_f16x2(v00, v01);
            a1 = cvt_f16x2(v10, v11);
            a2 = cvt_f16x2(v02, v03);
            a3 = cvt_f16x2(v12, v13);
        }

        const uint32_t bs = smb + B_OFF + buf * B_BUF + lB;
        #pragma unroll
        for (int nt = 0; nt < 7; ++nt) {
            uint32_t r0, r1, r2, r3;
            ldsm_x4(r0, r1, r2, r3, bs + nt * 512);
            mma16816h(acc[nt * 2],     a0, a1, a2, a3, r0, r1);
            mma16816h(acc[nt * 2 + 1], a0, a1, a2, a3, r2, r3);
        }

        CP_WAIT0();
        __syncthreads();
    }

    float* op = part + (size_t)blockIdx.y * PSTR;
    #pragma unroll
    for (int nt = 0; nt < 7; ++nt)
        #pragma unroll
        for (int nh = 0; nh < 2; ++nh) {
            const float* c = acc[nt * 2 + nh];
            int col = wn * 112 + nt * 16 + nh * 8 + tig * 2;
            size_t r = (size_t)(row0 + wm * 16 + g);
            *(float2*)&op[r * NPAD + col]       = make_float2(c[0], c[1]);
            *(float2*)&op[(r + 8) * NPAD + col] = make_float2(c[2], c[3]);
        }
}

// ===========================================================================
// CIN pooling + cin linear, reading K-split partials directly.
// ===========================================================================
__global__ void pool_kernel(const float* __restrict__ cin_lin_w,
                            const float* __restrict__ b0,
                            const float* __restrict__ b1,
                            const float* __restrict__ b2) {
    const int b = blockIdx.x;
    const int tid = threadIdx.x;

    float acc = 0.0f;
    for (int j = tid; j < 3 * Demb * 200; j += 256) {
        int l = j / 2000;
        int rem = j - l * 2000;
        int d = rem / 200;
        int h = rem - d * 200;
        size_t off = (size_t)(b * Demb + d) * NPAD + h;
        float w = cin_lin_w[l * 200 + h];
        float v = 0.0f;
        if (l == 0) {
            #pragma unroll
            for (int s = 0; s < SPLIT0; ++s) v += g_pA[(size_t)s * PSTR + off];
            if (d == 0) v += Demb * b0[h];
        } else if (l == 1) {
            #pragma unroll
            for (int s = 0; s < SPLIT1; ++s) v += g_pB[(size_t)s * PSTR + off];
            if (d == 0) v += Demb * b1[h];
        } else {
            #pragma unroll
            for (int s = 0; s < SPLIT1; ++s) v += g_pC[(size_t)s * PSTR + off];
            if (d == 0) v += Demb * b2[h];
        }
        acc += v * w;
    }
    __shared__ float red[256];
    red[tid] = acc;
    __syncthreads();
    for (int s = 128; s > 0; s >>= 1) {
        if (tid < s) red[tid] += red[tid + s];
        __syncthreads();
    }
    if (tid == 0) g_cinlogit[b] = red[0];
}

// ===========================================================================
// DNN GEMM + optional relu
// ===========================================================================
__global__ void dnn_gemm(const float* __restrict__ A,
                         const float* __restrict__ W,
                         const float* __restrict__ bias,
                         float* __restrict__ Out,
                         int K, int relu) {
    __shared__ float As[16 * 64];
    __shared__ float Bs[16 * 40];

    const int tid = threadIdx.x;
    const int row0 = blockIdx.x * 64;
    const int n0 = blockIdx.y * 40;
    const int tx = tid & 7;
    const int ty = tid >> 3;
    const int N = 400;

    float acc[2][5];
    #pragma unroll
    for (int m = 0; m < 2; ++m)
        #pragma unroll
        for (int q = 0; q < 5; ++q) acc[m][q] = 0.0f;

    for (int k0 = 0; k0 < K; k0 += 16) {
        __syncthreads();
        for (int idx = tid; idx < 64 * 16; idx += 256) {
            int r = idx >> 4, kk = idx & 15;
            int k = k0 + kk;
            As[kk * 64 + r] = (k < K) ? A[(size_t)(row0 + r) * K + k] : 0.0f;
        }
        for (int idx = tid; idx < 16 * 40; idx += 256) {
            int kk = idx / 40, q = idx - kk * 40;
            int k = k0 + kk;
            Bs[kk * 40 + q] = (k < K) ? W[(size_t)k * N + n0 + q] : 0.0f;
        }
        __syncthreads();

        #pragma unroll
        for (int kk = 0; kk < 16; ++kk) {
            float a0 = As[kk * 64 + ty * 2 + 0];
            float a1 = As[kk * 64 + ty * 2 + 1];
            float wv[5];
            #pragma unroll
            for (int q = 0; q < 5; ++q) wv[q] = Bs[kk * 40 + tx * 5 + q];
            #pragma unroll
            for (int q = 0; q < 5; ++q) {
                acc[0][q] += a0 * wv[q];
                acc[1][q] += a1 * wv[q];
            }
        }
    }

    #pragma unroll
    for (int m = 0; m < 2; ++m) {
        int r = row0 + ty * 2 + m;
        #pragma unroll
        for (int q = 0; q < 5; ++q) {
            int n = n0 + tx * 5 + q;
            float v = acc[m][q] + bias[n];
            if (relu) v = fmaxf(v, 0.0f);
            Out[(size_t)r * N + n] = v;
        }
    }
}

// ===========================================================================
// Final: dnn linear dot + linear partials + combine + sigmoid
// ===========================================================================
__global__ void final_kernel(const float* __restrict__ b_lin,
                             const float* __restrict__ cin_lin_b,
                             const float* __restrict__ dnn_lin_w,
                             const float* __restrict__ dnn_lin_b,
                             const float* __restrict__ pred_b,
                             float* __restrict__ out) {
    const int b = blockIdx.x;
    const int tid = threadIdx.x;
    float acc = 0.0f;
    for (int k = tid; k < 400; k += 128)
        acc += g_h1[(size_t)b * 400 + k] * dnn_lin_w[k];
    for (int f = tid; f < 27; f += 128)
        acc += g_linpart[f * Bsz + b];
    __shared__ float red[128];
    red[tid] = acc;
    __syncthreads();
    for (int s = 64; s > 0; s >>= 1) {
        if (tid < s) red[tid] += red[tid + s];
        __syncthreads();
    }
    if (tid == 0) {
        float z = red[0] + b_lin[0]
                + g_cinlogit[b] + cin_lin_b[0]
                + dnn_lin_b[0] + pred_b[0];
        out[b] = 1.0f / (1.0f + expf(-z));
    }
}

// ===========================================================================
// host launcher
// ===========================================================================
static int smem_cin(int JS, int KPER) {
    int cstr = JS + 1;
    int es_off = 64 * cstr * 4;
    int b_off = ((es_off + 64 * 39 * 4 + 127) / 128) * 128;
    int tab_off = b_off + 2 * (224 * 32);
    return tab_off + KPER * 4;
}

extern "C" void kernel_launch(void* const* d_in, const int* in_sizes, int n_in,
                              void* d_out, int out_size) {
    const float* x         = (const float*)d_in[0];
    const float* w_lin     = (const float*)d_in[1];
    const float* b_lin     = (const float*)d_in[2];
    const float* W_num     = (const float*)d_in[3];
    const float* W_cat     = (const float*)d_in[4];
    const float* cin_w0    = (const float*)d_in[5];
    const float* cin_b0    = (const float*)d_in[6];
    const float* cin_w1    = (const float*)d_in[7];
    const float* cin_b1    = (const float*)d_in[8];
    const float* cin_w2    = (const float*)d_in[9];
    const float* cin_b2    = (const float*)d_in[10];
    const float* cin_lin_w = (const float*)d_in[11];
    const float* cin_lin_b = (const float*)d_in[12];
    const float* dnn_w0    = (const float*)d_in[13];
    const float* dnn_b0    = (const float*)d_in[14];
    const float* dnn_w1    = (const float*)d_in[15];
    const float* dnn_b1    = (const float*)d_in[16];
    const float* dnn_lin_w = (const float*)d_in[17];
    const float* dnn_lin_b = (const float*)d_in[18];
    const float* pred_b    = (const float*)d_in[19];
    float* out = (float*)d_out;

    float *p_E_dm, *p_E_flat, *p_h0, *p_h1, *p_pA, *p_pB, *p_pC;
    cudaGetSymbolAddress((void**)&p_E_dm,   g_E_dm);
    cudaGetSymbolAddress((void**)&p_E_flat, g_E_flat);
    cudaGetSymbolAddress((void**)&p_h0,     g_h0);
    cudaGetSymbolAddress((void**)&p_h1,     g_h1);
    cudaGetSymbolAddress((void**)&p_pA,     g_pA);
    cudaGetSymbolAddress((void**)&p_pB,     g_pB);
    cudaGetSymbolAddress((void**)&p_pC,     g_pC);

    __half *p_W0, *p_W1, *p_W2;
    cudaGetSymbolAddress((void**)&p_W0, g_W0);
    cudaGetSymbolAddress((void**)&p_W1, g_W1);
    cudaGetSymbolAddress((void**)&p_W2, g_W2);

    const int SM0 = smem_cin(14, KPER0);
    const int SM1 = smem_cin(30, KPER1);
    cudaFuncSetAttribute(cin_mma<39,  KPER0, 14, 0>,      cudaFuncAttributeMaxDynamicSharedMemorySize, SM0);
    cudaFuncSetAttribute(cin_mma<200, KPER1, 30, SPLIT0>, cudaFuncAttributeMaxDynamicSharedMemorySize, SM1);
    cudaFuncSetAttribute(cin_mma<200, KPER1, 30, SPLIT1>, cudaFuncAttributeMaxDynamicSharedMemorySize, SM1);

    const int ROWB = Rrows / 64;   // 160

    numeric_kernel<<<Bsz / 128, 128>>>(x, w_lin, W_num);
    cat_kernel<<<dim3(Bsz / 128, NUM_CAT), 256>>>(x, w_lin, W_cat);
    convert_w<<<(KPAD0 * NPAD + 255) / 256, 256>>>(cin_w0, p_W0, 39,  KPAD0);
    convert_w<<<(KPAD1 * NPAD + 255) / 256, 256>>>(cin_w1, p_W1, 200, KPAD1);
    cin_mma<39,  KPER0, 14, 0><<<dim3(ROWB, SPLIT0), 256, SM0>>>(
        p_E_dm, nullptr, p_W0, p_pA);
    cin_mma<200, KPER1, 30, SPLIT0><<<dim3(ROWB, SPLIT1), 256, SM1>>>(
        p_pA, cin_b0, p_W1, p_pB);
    convert_w<<<(KPAD1 * NPAD + 255) / 256, 256>>>(cin_w2, p_W2, 200, KPAD1);
    cin_mma<200, KPER1, 30, SPLIT1><<<dim3(ROWB, SPLIT1), 256, SM1>>>(
        p_pB, cin_b1, p_W2, p_pC);
    pool_kernel<<<Bsz, 256>>>(cin_lin_w, cin_b0, cin_b1, cin_b2);
    dim3 dgrid(Bsz / 64, 400 / 40);
    dnn_gemm<<<dgrid, 256>>>(p_E_flat, dnn_w0, dnn_b0, p_h0, Mfld * Demb, 1);
    dnn_gemm<<<dgrid, 256>>>(p_h0, dnn_w1, dnn_b1, p_h1, 400, 1);
    final_kernel<<<Bsz, 128>>>(b_lin, cin_lin_b, dnn_lin_w, dnn_lin_b, pred_b, out);
}